// round 9
// baseline (speedup 1.0000x reference)
#include <cuda_runtime.h>

#define GH 96
#define GW 96
#define HW (GH*GW)
#define BSZ 8
#define LN 16
#define PN 16
#define NCELL (BSZ*GH*GW)   /* 73728 */
#define TPB 128
#define CPB 64              /* cells per block: 2 threads per cell (line-split) */
#define NBLK (NCELL/CPB)    /* 1152 */

__device__ float g_partials[NBLK];
__device__ unsigned int g_ticket;   // zero-init; last block resets it

__device__ __forceinline__ float asqrt(float x) {
    float r;
    asm("sqrt.approx.f32 %0, %1;" : "=f"(r) : "f"(x));
    return r;
}
__device__ __forceinline__ float arcp(float x) {
    float r;
    asm("rcp.approx.f32 %0, %1;" : "=f"(r) : "f"(x));
    return r;
}

__global__ __launch_bounds__(TPB, 6)
void yolino_main(const float* __restrict__ target, const float* __restrict__ pred,
                 float* __restrict__ out)
{
    // Pairing: lanes (2k, 2k+1) share one cell; g selects lines [8g, 8g+8).
    const int tid = threadIdx.x;
    const int g   = tid & 1;
    const int n   = blockIdx.x * CPB + (tid >> 1);   // grid cell

    const int w  = n % GW;
    const int t1 = n / GW;
    const int h  = t1 % GH;
    const int b  = t1 / GH;

    const int cell_off = h * GW + w;
    // This thread's 8 lines = channels [g*32, g*32+32)
    const float* tb = target + b * (64 * HW) + (g * 32) * HW + cell_off;
    const float* pb = pred   + b * (96 * HW) + cell_off;

    // 8 target lines in registers (32 regs).
    float tlv[8][4];
    #pragma unroll
    for (int l = 0; l < 8; ++l) {
        #pragma unroll
        for (int j = 0; j < 4; ++j)
            tlv[l][j] = tb[(l * 4 + j) * HW];
    }

    // Local valid-line mask (8 bits).
    unsigned tmask = 0;
    #pragma unroll
    for (int l = 0; l < 8; ++l) {
        float s = (tlv[l][0] + tlv[l][1]) + (tlv[l][2] + tlv[l][3]);
        if (s > 0.f) tmask |= (1u << l);
    }

    float loss = 0.f;

    // Prefetch predictor 0's six channels (partner lanes load same address ->
    // warp-level broadcast, still one memory transaction).
    float q0 = pb[0], q1 = pb[HW], q2 = pb[2 * HW],
          q3 = pb[3 * HW], q4 = pb[4 * HW], q5 = pb[5 * HW];

    #pragma unroll 1
    for (int p = 0; p < PN; ++p) {
        const float c0 = q0, c1 = q1, c2 = q2, c3 = q3, c4 = q4, c5 = q5;

        if (p + 1 < PN) {
            const float* nb = pb + (p + 1) * (6 * HW);
            q0 = nb[0];      q1 = nb[HW];     q2 = nb[2 * HW];
            q3 = nb[3 * HW]; q4 = nb[4 * HW]; q5 = nb[5 * HW];
        }

        // 8 independent distances.
        float d[8];
        #pragma unroll
        for (int l = 0; l < 8; ++l) {
            float dx1 = tlv[l][0] - c0, dy1 = tlv[l][1] - c1;
            float dx2 = tlv[l][2] - c2, dy2 = tlv[l][3] - c3;
            float s1 = fmaf(dx1, dx1, dy1 * dy1);
            float s2 = fmaf(dx2, dx2, dy2 * dy2);
            d[l] = asqrt(s1) + asqrt(s2);
        }

        // Partial tree min over this thread's 8 lines (depth 3).
        float mm0 = fminf(d[0], d[1]), mm1 = fminf(d[2], d[3]);
        float mm2 = fminf(d[4], d[5]), mm3 = fminf(d[6], d[7]);
        mm0 = fminf(mm0, mm2); mm1 = fminf(mm1, mm3);
        const float mh = fminf(mm0, mm1);

        // Exchange partial min with partner lane; both get the exact cell min.
        const float mo = __shfl_xor_sync(0xffffffffu, mh, 1);
        const float m  = fminf(mh, mo);

        // Local tie mask vs the exact global min (exact equality on stored d).
        unsigned a = 0;
        #pragma unroll
        for (int l = 0; l < 8; ++l)
            a |= (d[l] == m) ? (1u << l) : 0u;

        const int cl = __popc(a & tmask);
        const int co = __shfl_xor_sync(0xffffffffu, cl, 1);
        // thr = (m<2)?m:-1; distances >= 0 so thr=-1 selects nothing.
        const float cnt = (m < 2.f) ? (float)(cl + co) : 0.f;

        // Epilogue executed by BOTH partner threads with identical inputs:
        // every term is added exactly twice; final scale divides by 2.
        loss = fmaf(m, cnt, loss);                 // dist term (selected == m)

        float sig = arcp(1.f + __expf(-c4));       // sigmoid(conf)
        float e   = (cnt > 0.f) ? (sig - 1.f) : sig;
        loss = fmaf(e, e, loss);                   // conf term

        if (!(c5 > 0.f)) loss += cnt;              // cls term (hard=1 <=> c5>0)
    }

    // ---- block reduction (deterministic) ----
    #pragma unroll
    for (int o = 16; o > 0; o >>= 1)
        loss += __shfl_xor_sync(0xffffffffu, loss, o);

    __shared__ float sw[TPB / 32];
    __shared__ bool  s_last;
    const int lane = tid & 31;
    const int wid  = tid >> 5;
    if (lane == 0) sw[wid] = loss;
    __syncthreads();
    if (wid == 0) {
        float v = (lane < TPB / 32) ? sw[lane] : 0.f;
        #pragma unroll
        for (int o = 2; o > 0; o >>= 1)
            v += __shfl_xor_sync(0xffffffffu, v, o);
        if (lane == 0) {
            g_partials[blockIdx.x] = v;
            __threadfence();
            unsigned t = atomicAdd(&g_ticket, 1u);
            s_last = (t == NBLK - 1);
        }
    }
    __syncthreads();

    // ---- last block folds all partials into the output ----
    if (s_last) {
        __threadfence();  // acquire: make all g_partials visible
        const int t = tid;
        float v = 0.f;
        for (int i = t; i < NBLK; i += TPB)   // fixed order: deterministic
            v += g_partials[i];
        __shared__ float s[TPB];
        s[t] = v;
        __syncthreads();
        #pragma unroll
        for (int o = TPB / 2; o > 0; o >>= 1) {
            if (t < o) s[t] += s[t + o];
            __syncthreads();
        }
        if (t == 0) {
            // Every (cell,p) term was accumulated by both partner threads:
            // divide by 2, then by batch size.
            out[0] = s[0] * (1.0f / (2.0f * BSZ));
            g_ticket = 0;   // reset for the next (graph-replayed) launch
        }
    }
}

extern "C" void kernel_launch(void* const* d_in, const int* in_sizes, int n_in,
                              void* d_out, int out_size)
{
    const float* target = (const float*)d_in[0];
    const float* pred   = (const float*)d_in[1];
    float* out = (float*)d_out;

    yolino_main<<<NBLK, TPB>>>(target, pred, out);
}